// round 16
// baseline (speedup 1.0000x reference)
#include <cuda_runtime.h>
#include <cstddef>

// Mip chain: [6, 2048, 2048, 3] f32 -> repeated 2x2 avg pool down to 16.
// Output = concat(base, mip1..mip7).
// Single kernel + tiny memset node. mip7 accumulated via per-block atomicAdd
// (4 contributions of mip6*0.25 per mip7 px; reorder error ~1e-7 << 1e-3).

#define R0 2048
#define OFF1 75497472ull
#define OFF2 94371840ull
#define OFF3 99090432ull
#define OFF4 100270080ull
#define OFF5 100564992ull
#define OFF6 100638720ull
#define OFF7 100657152ull
#define MIP7_FLOATS (16 * 16 * 6 * 3)

// smem (floats): slab sums 16x192=3072 | m1 16x96=1536 | m2 16x48=768 |
//                m3 8x24=192 | m4 4x12=48 | m5 2x6=12
#define S_SLAB 0
#define S_M1   3072
#define S_M2   4608
#define S_M3   5376
#define S_M4   5568
#define S_M5   5616
#define A_SMEM 5628

__global__ __launch_bounds__(256) void mip_stageA(const float* __restrict__ base,
                                                  float* __restrict__ out) {
    __shared__ float sm[A_SMEM];
    const int f  = blockIdx.z;
    const int tX = blockIdx.x;   // 0..31
    const int tY = blockIdx.y;   // 0..31
    const int t  = threadIdx.x;  // 0..255

    // 768 units per 32-row slab: unit = (row-pair 0..15) * 48 + f4col
    int aa[3], cc[3];
    #pragma unroll
    for (int k = 0; k < 3; k++) {
        const int unit = k * 256 + t;
        aa[k] = unit / 48;
        cc[k] = unit - aa[k] * 48;
    }

    const size_t tile = ((size_t)(f * R0 + tY * 64) * R0 + tX * 64) * 3;

    // preload slab 0 (raw rows held in regs until L0 store)
    float4 va[3], vb[3];
    #pragma unroll
    for (int k = 0; k < 3; k++) {
        const size_t g0 = tile + (size_t)(2 * aa[k]) * (R0 * 3);
        va[k] = __ldcs(reinterpret_cast<const float4*>(base + g0) + cc[k]);
        vb[k] = __ldcs(reinterpret_cast<const float4*>(base + g0 + (size_t)(R0 * 3)) + cc[k]);
    }

    #pragma unroll
    for (int s = 0; s < 2; s++) {
        // ---- L0 copy + publish vertical sums ----
        #pragma unroll
        for (int k = 0; k < 3; k++) {
            const size_t g0 = tile + (size_t)(s * 32 + 2 * aa[k]) * (R0 * 3);
            __stcs(reinterpret_cast<float4*>(out + g0) + cc[k], va[k]);
            __stcs(reinterpret_cast<float4*>(out + g0 + (size_t)(R0 * 3)) + cc[k], vb[k]);
            float4 sv;
            sv.x = va[k].x + vb[k].x; sv.y = va[k].y + vb[k].y;
            sv.z = va[k].z + vb[k].z; sv.w = va[k].w + vb[k].w;
            reinterpret_cast<float4*>(sm + S_SLAB)[aa[k] * 48 + cc[k]] = sv;
        }
        __syncthreads();

        // ---- prefetch slab 1 while mip1/mip2 run ----
        if (s == 0) {
            #pragma unroll
            for (int k = 0; k < 3; k++) {
                const size_t g0 = tile + (size_t)(32 + 2 * aa[k]) * (R0 * 3);
                va[k] = __ldcs(reinterpret_cast<const float4*>(base + g0) + cc[k]);
                vb[k] = __ldcs(reinterpret_cast<const float4*>(base + g0 + (size_t)(R0 * 3)) + cc[k]);
            }
        }

        // ---- mip1: 16 rows x 32 px, 2 px per thread ----
        {
            const int r1 = t >> 4;            // 0..15
            const int c1 = (t & 15) * 2;      // even
            const float* in = sm + S_SLAB + r1 * 192 + c1 * 6;  // vertical sums
            const float v0 = (in[0] + in[3]) * 0.25f;
            const float v1 = (in[1] + in[4]) * 0.25f;
            const float v2 = (in[2] + in[5]) * 0.25f;
            const float v3 = (in[6] + in[9]) * 0.25f;
            const float v4 = (in[7] + in[10]) * 0.25f;
            const float v5 = (in[8] + in[11]) * 0.25f;
            const int y1 = tY * 32 + s * 16 + r1;
            const int x1 = tX * 32 + c1;
            float2* o = reinterpret_cast<float2*>(out + OFF1 +
                          ((size_t)(f * 1024 + y1) * 1024 + x1) * 3);
            __stcs(o,     make_float2(v0, v1));
            __stcs(o + 1, make_float2(v2, v3));
            __stcs(o + 2, make_float2(v4, v5));
            float* m1 = sm + S_M1 + r1 * 96 + c1 * 3;
            m1[0] = v0; m1[1] = v1; m1[2] = v2;
            m1[3] = v3; m1[4] = v4; m1[5] = v5;
        }
        __syncthreads();

        // ---- mip2: 8 rows x 16 px (threads 0..127) ----
        if (t < 128) {
            const int r2 = t >> 4;            // 0..7
            const int c2 = t & 15;
            const float* ra = sm + S_M1 + (2 * r2) * 96 + c2 * 6;
            const float* rb = ra + 96;
            const float vr = (ra[0] + ra[3] + rb[0] + rb[3]) * 0.25f;
            const float vg = (ra[1] + ra[4] + rb[1] + rb[4]) * 0.25f;
            const float vb2 = (ra[2] + ra[5] + rb[2] + rb[5]) * 0.25f;
            const int y2 = tY * 16 + s * 8 + r2;
            const int x2 = tX * 16 + c2;
            float* o = out + OFF2 + ((size_t)(f * 512 + y2) * 512 + x2) * 3;
            __stcs(o,     vr);
            __stcs(o + 1, vg);
            __stcs(o + 2, vb2);
            float* m2 = sm + S_M2 + (s * 8 + r2) * 48 + c2 * 3;
            m2[0] = vr; m2[1] = vg; m2[2] = vb2;
        }
        __syncthreads();    // slab buf + m1 free for next iteration
    }

    // ---- mip3: 8x8 (threads 0..63) ----
    if (t < 64) {
        const int r = t >> 3, c = t & 7;
        const float* ra = sm + S_M2 + (2 * r) * 48 + c * 6;
        const float* rb = ra + 48;
        const float vr = (ra[0] + ra[3] + rb[0] + rb[3]) * 0.25f;
        const float vg = (ra[1] + ra[4] + rb[1] + rb[4]) * 0.25f;
        const float vb2 = (ra[2] + ra[5] + rb[2] + rb[5]) * 0.25f;
        float* o = out + OFF3 + ((size_t)(f * 256 + tY * 8 + r) * 256 + tX * 8 + c) * 3;
        __stcs(o, vr); __stcs(o + 1, vg); __stcs(o + 2, vb2);
        float* m3 = sm + S_M3 + (r * 8 + c) * 3;
        m3[0] = vr; m3[1] = vg; m3[2] = vb2;
    }
    __syncthreads();

    // ---- mip4: 4x4 (threads 0..15) ----
    if (t < 16) {
        const int r = t >> 2, c = t & 3;
        const float* ra = sm + S_M3 + ((2 * r) * 8 + 2 * c) * 3;
        const float* rb = ra + 8 * 3;
        const float vr = (ra[0] + ra[3] + rb[0] + rb[3]) * 0.25f;
        const float vg = (ra[1] + ra[4] + rb[1] + rb[4]) * 0.25f;
        const float vb2 = (ra[2] + ra[5] + rb[2] + rb[5]) * 0.25f;
        float* o = out + OFF4 + ((size_t)(f * 128 + tY * 4 + r) * 128 + tX * 4 + c) * 3;
        o[0] = vr; o[1] = vg; o[2] = vb2;
        float* m4 = sm + S_M4 + (r * 4 + c) * 3;
        m4[0] = vr; m4[1] = vg; m4[2] = vb2;
    }
    __syncthreads();

    // ---- mip5: 2x2 (threads 0..3) ----
    if (t < 4) {
        const int r = t >> 1, c = t & 1;
        const float* ra = sm + S_M4 + ((2 * r) * 4 + 2 * c) * 3;
        const float* rb = ra + 4 * 3;
        const float vr = (ra[0] + ra[3] + rb[0] + rb[3]) * 0.25f;
        const float vg = (ra[1] + ra[4] + rb[1] + rb[4]) * 0.25f;
        const float vb2 = (ra[2] + ra[5] + rb[2] + rb[5]) * 0.25f;
        float* o = out + OFF5 + ((size_t)(f * 64 + tY * 2 + r) * 64 + tX * 2 + c) * 3;
        o[0] = vr; o[1] = vg; o[2] = vb2;
        float* m5 = sm + S_M5 + (r * 2 + c) * 3;
        m5[0] = vr; m5[1] = vg; m5[2] = vb2;
    }
    __syncthreads();

    // ---- mip6 (1 px, thread 0) + mip7 contribution via atomicAdd ----
    if (t == 0) {
        const float* m5 = sm + S_M5;
        float* o = out + OFF6 + ((size_t)(f * 32 + tY) * 32 + tX) * 3;
        float* o7 = out + OFF7 + ((size_t)(f * 16 + (tY >> 1)) * 16 + (tX >> 1)) * 3;
        #pragma unroll
        for (int c = 0; c < 3; c++) {
            const float v = (m5[c] + m5[3 + c] + m5[6 + c] + m5[9 + c]) * 0.25f;
            o[c] = v;
            atomicAdd(o7 + c, v * 0.25f);   // REDG, spread addrs, 4 adds/px
        }
    }
}

extern "C" void kernel_launch(void* const* d_in, const int* in_sizes, int n_in,
                              void* d_out, int out_size) {
    const float* base = (const float*)d_in[0];
    float* out = (float*)d_out;

    // zero mip7 region (d_out is poisoned); tiny CE node, precedes stageA.
    cudaMemsetAsync(out + OFF7, 0, MIP7_FLOATS * sizeof(float), 0);

    dim3 gA(32, 32, 6);
    mip_stageA<<<gA, 256>>>(base, out);
}

// round 17
// speedup vs baseline: 1.0158x; 1.0158x over previous
#include <cuda_runtime.h>
#include <cstddef>

// Mip chain: [6, 2048, 2048, 3] f32 -> repeated 2x2 avg pool down to 16.
// Output = concat(base, mip1..mip7).
// Graph: zero_mip7 (tiny kernel) -> stageA (PDL; waits only before mip7 atomics).

#define R0 2048
#define OFF1 75497472ull
#define OFF2 94371840ull
#define OFF3 99090432ull
#define OFF4 100270080ull
#define OFF5 100564992ull
#define OFF6 100638720ull
#define OFF7 100657152ull
#define MIP7_FLOAT4 1152   // 6*16*16*3 floats / 4

// smem (floats): slab sums 16x192=3072 | m1 16x96=1536 | m2 16x48=768 |
//                m3 8x24=192 | m4 4x12=48 | m5 2x6=12
#define S_SLAB 0
#define S_M1   3072
#define S_M2   4608
#define S_M3   5376
#define S_M4   5568
#define S_M5   5616
#define A_SMEM 5628

// ---- tiny node: zero the mip7 region (poisoned by harness) ----
__global__ __launch_bounds__(192) void zero_mip7(float* __restrict__ out) {
    float4* p = reinterpret_cast<float4*>(out + OFF7);
    const int i = blockIdx.x * 192 + threadIdx.x;   // 6*192 = 1152
    p[i] = make_float4(0.f, 0.f, 0.f, 0.f);
    // release dependents early (memory flushed at signal per PDL semantics)
    asm volatile("griddepcontrol.launch_dependents;");
}

__global__ __launch_bounds__(256) void mip_stageA(const float* __restrict__ base,
                                                  float* __restrict__ out) {
    __shared__ float sm[A_SMEM];
    const int f  = blockIdx.z;
    const int tX = blockIdx.x;   // 0..31
    const int tY = blockIdx.y;   // 0..31
    const int t  = threadIdx.x;  // 0..255

    // 768 units per 32-row slab: unit = (row-pair 0..15) * 48 + f4col
    int aa[3], cc[3];
    #pragma unroll
    for (int k = 0; k < 3; k++) {
        const int unit = k * 256 + t;
        aa[k] = unit / 48;
        cc[k] = unit - aa[k] * 48;
    }

    const size_t tile = ((size_t)(f * R0 + tY * 64) * R0 + tX * 64) * 3;

    // preload slab 0 (raw rows held in regs until L0 store)
    float4 va[3], vb[3];
    #pragma unroll
    for (int k = 0; k < 3; k++) {
        const size_t g0 = tile + (size_t)(2 * aa[k]) * (R0 * 3);
        va[k] = __ldcs(reinterpret_cast<const float4*>(base + g0) + cc[k]);
        vb[k] = __ldcs(reinterpret_cast<const float4*>(base + g0 + (size_t)(R0 * 3)) + cc[k]);
    }

    #pragma unroll
    for (int s = 0; s < 2; s++) {
        // ---- L0 copy + publish vertical sums ----
        #pragma unroll
        for (int k = 0; k < 3; k++) {
            const size_t g0 = tile + (size_t)(s * 32 + 2 * aa[k]) * (R0 * 3);
            __stcs(reinterpret_cast<float4*>(out + g0) + cc[k], va[k]);
            __stcs(reinterpret_cast<float4*>(out + g0 + (size_t)(R0 * 3)) + cc[k], vb[k]);
            float4 sv;
            sv.x = va[k].x + vb[k].x; sv.y = va[k].y + vb[k].y;
            sv.z = va[k].z + vb[k].z; sv.w = va[k].w + vb[k].w;
            reinterpret_cast<float4*>(sm + S_SLAB)[aa[k] * 48 + cc[k]] = sv;
        }
        __syncthreads();

        // ---- prefetch slab 1 while mip1/mip2 run ----
        if (s == 0) {
            #pragma unroll
            for (int k = 0; k < 3; k++) {
                const size_t g0 = tile + (size_t)(32 + 2 * aa[k]) * (R0 * 3);
                va[k] = __ldcs(reinterpret_cast<const float4*>(base + g0) + cc[k]);
                vb[k] = __ldcs(reinterpret_cast<const float4*>(base + g0 + (size_t)(R0 * 3)) + cc[k]);
            }
        }

        // ---- mip1: 16 rows x 32 px, 2 px per thread ----
        {
            const int r1 = t >> 4;            // 0..15
            const int c1 = (t & 15) * 2;      // even
            const float* in = sm + S_SLAB + r1 * 192 + c1 * 6;  // vertical sums
            const float v0 = (in[0] + in[3]) * 0.25f;
            const float v1 = (in[1] + in[4]) * 0.25f;
            const float v2 = (in[2] + in[5]) * 0.25f;
            const float v3 = (in[6] + in[9]) * 0.25f;
            const float v4 = (in[7] + in[10]) * 0.25f;
            const float v5 = (in[8] + in[11]) * 0.25f;
            const int y1 = tY * 32 + s * 16 + r1;
            const int x1 = tX * 32 + c1;
            float2* o = reinterpret_cast<float2*>(out + OFF1 +
                          ((size_t)(f * 1024 + y1) * 1024 + x1) * 3);
            __stcs(o,     make_float2(v0, v1));
            __stcs(o + 1, make_float2(v2, v3));
            __stcs(o + 2, make_float2(v4, v5));
            float* m1 = sm + S_M1 + r1 * 96 + c1 * 3;
            m1[0] = v0; m1[1] = v1; m1[2] = v2;
            m1[3] = v3; m1[4] = v4; m1[5] = v5;
        }
        __syncthreads();

        // ---- mip2: 8 rows x 16 px (threads 0..127) ----
        if (t < 128) {
            const int r2 = t >> 4;            // 0..7
            const int c2 = t & 15;
            const float* ra = sm + S_M1 + (2 * r2) * 96 + c2 * 6;
            const float* rb = ra + 96;
            const float vr = (ra[0] + ra[3] + rb[0] + rb[3]) * 0.25f;
            const float vg = (ra[1] + ra[4] + rb[1] + rb[4]) * 0.25f;
            const float vb2 = (ra[2] + ra[5] + rb[2] + rb[5]) * 0.25f;
            const int y2 = tY * 16 + s * 8 + r2;
            const int x2 = tX * 16 + c2;
            float* o = out + OFF2 + ((size_t)(f * 512 + y2) * 512 + x2) * 3;
            __stcs(o,     vr);
            __stcs(o + 1, vg);
            __stcs(o + 2, vb2);
            float* m2 = sm + S_M2 + (s * 8 + r2) * 48 + c2 * 3;
            m2[0] = vr; m2[1] = vg; m2[2] = vb2;
        }
        __syncthreads();    // slab buf + m1 free for next iteration
    }

    // ---- mip3: 8x8 (threads 0..63) ----
    if (t < 64) {
        const int r = t >> 3, c = t & 7;
        const float* ra = sm + S_M2 + (2 * r) * 48 + c * 6;
        const float* rb = ra + 48;
        const float vr = (ra[0] + ra[3] + rb[0] + rb[3]) * 0.25f;
        const float vg = (ra[1] + ra[4] + rb[1] + rb[4]) * 0.25f;
        const float vb2 = (ra[2] + ra[5] + rb[2] + rb[5]) * 0.25f;
        float* o = out + OFF3 + ((size_t)(f * 256 + tY * 8 + r) * 256 + tX * 8 + c) * 3;
        __stcs(o, vr); __stcs(o + 1, vg); __stcs(o + 2, vb2);
        float* m3 = sm + S_M3 + (r * 8 + c) * 3;
        m3[0] = vr; m3[1] = vg; m3[2] = vb2;
    }
    __syncthreads();

    // ---- mip4: 4x4 (threads 0..15) ----
    if (t < 16) {
        const int r = t >> 2, c = t & 3;
        const float* ra = sm + S_M3 + ((2 * r) * 8 + 2 * c) * 3;
        const float* rb = ra + 8 * 3;
        const float vr = (ra[0] + ra[3] + rb[0] + rb[3]) * 0.25f;
        const float vg = (ra[1] + ra[4] + rb[1] + rb[4]) * 0.25f;
        const float vb2 = (ra[2] + ra[5] + rb[2] + rb[5]) * 0.25f;
        float* o = out + OFF4 + ((size_t)(f * 128 + tY * 4 + r) * 128 + tX * 4 + c) * 3;
        o[0] = vr; o[1] = vg; o[2] = vb2;
        float* m4 = sm + S_M4 + (r * 4 + c) * 3;
        m4[0] = vr; m4[1] = vg; m4[2] = vb2;
    }
    __syncthreads();

    // ---- mip5: 2x2 (threads 0..3) ----
    if (t < 4) {
        const int r = t >> 1, c = t & 1;
        const float* ra = sm + S_M4 + ((2 * r) * 4 + 2 * c) * 3;
        const float* rb = ra + 4 * 3;
        const float vr = (ra[0] + ra[3] + rb[0] + rb[3]) * 0.25f;
        const float vg = (ra[1] + ra[4] + rb[1] + rb[4]) * 0.25f;
        const float vb2 = (ra[2] + ra[5] + rb[2] + rb[5]) * 0.25f;
        float* o = out + OFF5 + ((size_t)(f * 64 + tY * 2 + r) * 64 + tX * 2 + c) * 3;
        o[0] = vr; o[1] = vg; o[2] = vb2;
        float* m5 = sm + S_M5 + (r * 2 + c) * 3;
        m5[0] = vr; m5[1] = vg; m5[2] = vb2;
    }
    __syncthreads();

    // ---- mip6 (1 px, thread 0) + mip7 contribution via atomicAdd ----
    if (t == 0) {
        const float* m5 = sm + S_M5;
        float* o = out + OFF6 + ((size_t)(f * 32 + tY) * 32 + tX) * 3;
        float* o7 = out + OFF7 + ((size_t)(f * 16 + (tY >> 1)) * 16 + (tX >> 1)) * 3;
        // visibility of zero_mip7's stores before our atomics (PDL wait;
        // long signaled by the time any CTA reaches here — near-zero cost)
        asm volatile("griddepcontrol.wait;");
        #pragma unroll
        for (int c = 0; c < 3; c++) {
            const float v = (m5[c] + m5[3 + c] + m5[6 + c] + m5[9 + c]) * 0.25f;
            o[c] = v;
            atomicAdd(o7 + c, v * 0.25f);   // REDG, spread addrs, 4 adds/px
        }
    }
}

extern "C" void kernel_launch(void* const* d_in, const int* in_sizes, int n_in,
                              void* d_out, int out_size) {
    const float* base = (const float*)d_in[0];
    float* out = (float*)d_out;

    // tiny kernel node instead of CE memset (CE small-op latency ~7us)
    zero_mip7<<<6, 192>>>(out);

    // stageA as PDL secondary: prelaunches/overlaps with zero_mip7.
    cudaLaunchConfig_t cfg = {};
    cfg.gridDim = dim3(32, 32, 6);
    cfg.blockDim = dim3(256, 1, 1);
    cfg.dynamicSmemBytes = 0;
    cfg.stream = 0;
    cudaLaunchAttribute attrs[1];
    attrs[0].id = cudaLaunchAttributeProgrammaticStreamSerialization;
    attrs[0].val.programmaticStreamSerializationAllowed = 1;
    cfg.attrs = attrs;
    cfg.numAttrs = 1;
    cudaLaunchKernelEx(&cfg, mip_stageA, base, out);
}